// round 3
// baseline (speedup 1.0000x reference)
#include <cuda_runtime.h>

// ---------------------------------------------------------------------------
// KF: batched square-root Kalman filter. B=2048, T=1000, n=d=8.
//  riccati  : sequential P/K/A recursion (batch-independent), freeze on conv.
//  fill     : parallel broadcast of frozen A,K,P to t >= t_conv.
//  wprep    : per-chunk backward suffix weights W and chunk transitions Phi.
//  ends     : e_{b,c} = sum_j W_{c,j} y_{c,j}  (fully parallel).
//  combine  : chunk-entry-state scan over C chunks per batch (tiny).
//  scan     : per (batch,chunk) LCH-step recurrence, writes traj.
// ---------------------------------------------------------------------------

#define LCH  40
#define TMAX 1024
#define CMAX ((TMAX + LCH - 1) / LCH)
#define BMAX 2048

__device__ __align__(16) float g_AK[TMAX * 128];        // per t: A[64], K[64]
__device__ __align__(16) float g_W[TMAX * 64];          // W per global step
__device__ __align__(16) float g_Phi[CMAX * 64];        // chunk transition
__device__ __align__(16) float g_E[(size_t)CMAX * BMAX * 8];
__device__ __align__(16) float g_X[(size_t)CMAX * BMAX * 8];
__device__ float g_frozen[192];                          // A,K,P
__device__ int   g_tconv;

// ============================ riccati ======================================

__global__ void __launch_bounds__(64) riccati_kernel(
    const float* __restrict__ Fg, const float* __restrict__ Gg,
    const float* __restrict__ Hg, const float* __restrict__ Qg,
    const float* __restrict__ Rg, const float* __restrict__ P0g,
    float* __restrict__ Ps_out, int T)
{
    __shared__ float sF[72], sHF[72], sGQG[72], sC1[72], sC2[72];
    __shared__ float sP[72], sU[72], sV[72], sPn[72], sT2[72], sS[72];
    __shared__ float sK[72], sTmp[72];
    __shared__ float sRed[4];
    __shared__ int   sFlag;

    const int tid = threadIdx.x;
    const int i = tid >> 3, j = tid & 7;
    const int ij = i * 9 + j;

    // inputs: sF=F, sTmp=G, sU=Q, sC2=R, sP=P0, sV=H
    sF[ij] = Fg[tid]; sTmp[ij] = Gg[tid]; sU[ij] = Qg[tid];
    sC2[ij] = Rg[tid]; sP[ij] = P0g[tid]; sV[ij] = Hg[tid];
    if (tid == 0) sFlag = 0;
    __syncthreads();

    // GQ -> sPn ; HF -> sHF
    {
        float a = 0.f, b = 0.f;
        #pragma unroll
        for (int k = 0; k < 8; k++) {
            a += sTmp[i*9+k] * sU[k*9+j];
            b += sV[i*9+k]   * sF[k*9+j];
        }
        sPn[ij] = a; sHF[ij] = b;
    }
    __syncthreads();
    // GQG = GQ * G^T
    {
        float a = 0.f;
        #pragma unroll
        for (int k = 0; k < 8; k++) a += sPn[i*9+k] * sTmp[j*9+k];
        sGQG[ij] = a;
    }
    __syncthreads();
    // C1 = H * GQG
    {
        float a = 0.f;
        #pragma unroll
        for (int k = 0; k < 8; k++) a += sV[i*9+k] * sGQG[k*9+j];
        sC1[ij] = a;
    }
    __syncthreads();
    // C2 = C1 * H^T + R
    {
        float a = sC2[ij];
        #pragma unroll
        for (int k = 0; k < 8; k++) a += sC1[i*9+k] * sV[j*9+k];
        __syncthreads();
        sC2[ij] = a;
    }
    __syncthreads();

    int conv = 0;
    bool frozen = false;
    for (int t = 0; t < T; t++) {
        // S1: U = F*P ; V = HF*P
        {
            float a = 0.f, b = 0.f;
            #pragma unroll
            for (int k = 0; k < 8; k++) {
                float p = sP[k*9+j];
                a = fmaf(sF[i*9+k],  p, a);
                b = fmaf(sHF[i*9+k], p, b);
            }
            sU[ij] = a; sV[ij] = b;
        }
        __syncthreads();
        // S2: Pn = U*F^T + GQG ; T2 = V*F^T + C1 ; S = V*HF^T + C2
        {
            float pn = sGQG[ij], t2 = sC1[ij], s = sC2[ij];
            #pragma unroll
            for (int k = 0; k < 8; k++) {
                float fk = sF[j*9+k];
                float vk = sV[i*9+k];
                pn = fmaf(sU[i*9+k], fk, pn);
                t2 = fmaf(vk, fk, t2);
                s  = fmaf(vk, sHF[j*9+k], s);
            }
            sPn[ij] = pn; sT2[ij] = t2; sS[ij] = s;
        }
        __syncthreads();
        // GJ on [S | T2]: 16 lanes, lane c owns a column; solves S X = T2.
        if (tid < 16) {
            float a[8];
            #pragma unroll
            for (int r = 0; r < 8; r++)
                a[r] = (tid < 8) ? sS[r*9+tid] : sT2[r*9+(tid-8)];
            #pragma unroll
            for (int p = 0; p < 8; p++) {
                float c[8];
                #pragma unroll
                for (int r = 0; r < 8; r++)
                    c[r] = __shfl_sync(0x0000FFFFu, a[r], p, 16);
                float pr = 1.0f / c[p];
                a[p] *= pr;
                #pragma unroll
                for (int r = 0; r < 8; r++)
                    if (r != p) a[r] = fmaf(-c[r], a[p], a[r]);
            }
            if (tid >= 8) {
                const int row = tid - 8;
                #pragma unroll
                for (int r = 0; r < 8; r++) sK[row*9 + r] = a[r];
            }
        }
        __syncthreads();
        // P+ = Pn - K*T2 ; A = F - K*HF
        float krow[8];
        #pragma unroll
        for (int k = 0; k < 8; k++) krow[k] = sK[i*9+k];
        float pp = sPn[ij], aa = sF[ij];
        #pragma unroll
        for (int k = 0; k < 8; k++) {
            pp = fmaf(-krow[k], sT2[k*9+j], pp);
            aa = fmaf(-krow[k], sHF[k*9+j], aa);
        }
        sTmp[ij] = pp;
        __syncthreads();
        float pnew = 0.5f * (pp + sTmp[j*9+i]);
        float pold = sP[ij];
        sP[ij] = pnew;

        Ps_out[(size_t)t*64 + tid]          = pnew;
        g_AK[(size_t)t*128 + i*8 + j]       = aa;
        g_AK[(size_t)t*128 + 64 + i*8 + j]  = krow[j];

        // convergence: max|dP| vs max|P|
        float dm = fabsf(pnew - pold);
        float pm = fabsf(pnew);
        #pragma unroll
        for (int o = 16; o > 0; o >>= 1) {
            dm = fmaxf(dm, __shfl_xor_sync(0xFFFFFFFFu, dm, o));
            pm = fmaxf(pm, __shfl_xor_sync(0xFFFFFFFFu, pm, o));
        }
        if ((tid & 31) == 0) { sRed[(tid>>5)*2] = dm; sRed[(tid>>5)*2+1] = pm; }
        __syncthreads();
        if (tid == 0) {
            float d = fmaxf(sRed[0], sRed[2]);
            float p = fmaxf(sRed[1], sRed[3]);
            if (t >= 24 && d < 3e-5f * p) conv++; else conv = 0;
            sFlag = (conv >= 4) ? 1 : 0;
        }
        __syncthreads();
        if (sFlag) {
            g_frozen[tid]       = aa;
            g_frozen[64 + tid]  = krow[j];
            g_frozen[128 + tid] = pnew;
            if (tid == 0) g_tconv = t + 1;
            frozen = true;
            break;
        }
    }
    if (!frozen && tid == 0) g_tconv = T;
}

// ============================ fill =========================================

__global__ void __launch_bounds__(256) fill_kernel(float* __restrict__ Ps_out, int T)
{
    const int tc = g_tconv;
    const int idx = blockIdx.x * 256 + threadIdx.x;
    const int t = idx / 192, e = idx - t * 192;
    if (t >= T || t < tc) return;
    const float v = g_frozen[e];
    if (e < 128) g_AK[(size_t)t*128 + e] = v;
    else         Ps_out[(size_t)t*64 + (e - 128)] = v;
}

// ============================ wprep ========================================

__global__ void __launch_bounds__(64) wprep_kernel(int T)
{
    const int c = blockIdx.x;
    const int L0 = c * LCH;
    const int Lc = min(LCH, T - L0);
    __shared__ float sM[2][72], sA[72], sK2[72];
    const int tid = threadIdx.x;
    const int i = tid >> 3, j = tid & 7;
    const int ij = i * 9 + j;

    sM[0][ij] = (i == j) ? 1.f : 0.f;
    __syncthreads();
    int pb = 0;
    for (int jj = Lc - 1; jj >= 0; jj--) {
        const int t = L0 + jj;
        sA[ij]  = g_AK[(size_t)t*128 + i*8 + j];
        sK2[ij] = g_AK[(size_t)t*128 + 64 + i*8 + j];
        __syncthreads();
        float w = 0.f, m = 0.f;
        #pragma unroll
        for (int k = 0; k < 8; k++) {
            float mk = sM[pb][i*9+k];
            w = fmaf(mk, sK2[k*9+j], w);
            m = fmaf(mk, sA[k*9+j],  m);
        }
        g_W[(size_t)t*64 + i*8 + j] = w;
        sM[pb ^ 1][ij] = m;
        pb ^= 1;
        __syncthreads();
    }
    g_Phi[c*64 + i*8 + j] = sM[pb][ij];
}

// ============================ ends =========================================

__global__ void __launch_bounds__(256) ends_kernel(
    const float* __restrict__ Y, int B, int T)
{
    const int c = blockIdx.x;
    const int L0 = c * LCH;
    const int Lc = min(LCH, T - L0);
    __shared__ __align__(16) float sW[LCH * 64];
    const int tid = threadIdx.x;
    for (int e = tid; e < Lc * 16; e += 256)
        ((float4*)sW)[e] = ((const float4*)(g_W + (size_t)L0 * 64))[e];
    __syncthreads();

    const int li = tid & 7;
    const int b = blockIdx.y * 32 + (tid >> 3);
    const bool ok = (b < B);
    const float* yb = Y + ((size_t)(ok ? b : 0) * T + L0) * 8 + li;

    float a0 = 0.f, a1 = 0.f;
    #pragma unroll 4
    for (int jj = 0; jj < Lc; jj++) {
        float yv = yb[(size_t)jj * 8];
        const float* wr = sW + jj * 64 + li * 8;
        #pragma unroll
        for (int k = 0; k < 8; k++) {
            float yk = __shfl_sync(0xFFFFFFFFu, yv, k, 8);
            if (k & 1) a1 = fmaf(wr[k], yk, a1);
            else       a0 = fmaf(wr[k], yk, a0);
        }
    }
    if (ok) g_E[((size_t)c * B + b) * 8 + li] = a0 + a1;
}

// ============================ combine ======================================

__global__ void __launch_bounds__(256) combine_kernel(
    const float* __restrict__ x0, int B, int C)
{
    __shared__ float sPhi[CMAX * 64];
    const int tid = threadIdx.x;
    for (int e = tid; e < C * 64; e += 256) sPhi[e] = g_Phi[e];
    __syncthreads();

    const int idx = blockIdx.x * 256 + tid;
    const int li = idx & 7;
    const int b = idx >> 3;
    const bool ok = (b < B);
    const int bs = ok ? b : 0;

    float ev[CMAX];
    #pragma unroll
    for (int c = 0; c < CMAX; c++)
        ev[c] = (c < C) ? g_E[((size_t)c * B + bs) * 8 + li] : 0.f;

    float x = x0[bs * 8 + li];
    #pragma unroll
    for (int c = 0; c < CMAX; c++) {
        if (c < C) {
            if (ok) g_X[((size_t)c * B + b) * 8 + li] = x;
            const float* pr = sPhi + c * 64 + li * 8;
            float xa0 = 0.f, xa1 = 0.f;
            #pragma unroll
            for (int k = 0; k < 8; k++) {
                float xk = __shfl_sync(0xFFFFFFFFu, x, k, 8);
                if (k & 1) xa1 = fmaf(pr[k], xk, xa1);
                else       xa0 = fmaf(pr[k], xk, xa0);
            }
            x = (xa0 + xa1) + ev[c];
        }
    }
}

// ============================ scan =========================================

__global__ void __launch_bounds__(256) scan_kernel(
    const float* __restrict__ Y, float* __restrict__ traj, int B, int T)
{
    const int c = blockIdx.x;
    const int L0 = c * LCH;
    const int Lc = min(LCH, T - L0);
    __shared__ __align__(16) float sAK[LCH * 128];
    const int tid = threadIdx.x;
    for (int e = tid; e < Lc * 32; e += 256)
        ((float4*)sAK)[e] = ((const float4*)(g_AK + (size_t)L0 * 128))[e];
    __syncthreads();

    const int li = tid & 7;
    const int b = blockIdx.y * 32 + (tid >> 3);
    const bool ok = (b < B);
    const int bs = ok ? b : 0;

    float x = g_X[((size_t)c * B + bs) * 8 + li];
    const float* yb = Y    + ((size_t)bs * T + L0) * 8 + li;
    float*       ob = traj + ((size_t)bs * T + L0) * 8 + li;

    float yr[8];
    #pragma unroll
    for (int u = 0; u < 8; u++) {
        int jj = (u < Lc) ? u : Lc - 1;
        yr[u] = yb[(size_t)jj * 8];
    }

    int jj = 0;
    const int ngr = (Lc + 7) / 8;
    for (int g = 0; g < ngr; g++) {
        #pragma unroll
        for (int u = 0; u < 8; u++) {
            if (jj < Lc) {
                const float* ar = sAK + jj * 128 + li * 8;
                const float* kr = ar + 64;
                float yv = yr[u];
                float k0 = 0.f, k1 = 0.f, x0a = 0.f, x1a = 0.f;
                #pragma unroll
                for (int k = 0; k < 8; k++) {
                    float yk = __shfl_sync(0xFFFFFFFFu, yv, k, 8);
                    float xk = __shfl_sync(0xFFFFFFFFu, x,  k, 8);
                    if (k < 4) { k0 = fmaf(kr[k], yk, k0); x0a = fmaf(ar[k], xk, x0a); }
                    else       { k1 = fmaf(kr[k], yk, k1); x1a = fmaf(ar[k], xk, x1a); }
                }
                x = (k0 + x0a) + (k1 + x1a);
                if (ok) ob[(size_t)jj * 8] = x;
                int tn = jj + 8; if (tn >= Lc) tn = Lc - 1;
                yr[u] = yb[(size_t)tn * 8];
                jj++;
            }
        }
    }
}

// ============================ launch =======================================

extern "C" void kernel_launch(void* const* d_in, const int* in_sizes, int n_in,
                              void* d_out, int out_size)
{
    const float* Y  = (const float*)d_in[0];
    const float* F  = (const float*)d_in[1];
    const float* G  = (const float*)d_in[2];
    const float* H  = (const float*)d_in[3];
    const float* Q  = (const float*)d_in[4];
    const float* R  = (const float*)d_in[5];
    const float* x0 = (const float*)d_in[6];
    const float* P0 = (const float*)d_in[7];

    const int B = in_sizes[6] / 8;
    const int T = in_sizes[0] / (B * 8);
    const int C = (T + LCH - 1) / LCH;

    float* traj = (float*)d_out;                 // (B, T, 8)
    float* Ps   = traj + (size_t)B * T * 8;      // (T, 8, 8)

    riccati_kernel<<<1, 64>>>(F, G, H, Q, R, P0, Ps, T);
    fill_kernel<<<(T * 192 + 255) / 256, 256>>>(Ps, T);
    wprep_kernel<<<C, 64>>>(T);
    {
        dim3 grid(C, (B + 31) / 32);
        ends_kernel<<<grid, 256>>>(Y, B, T);
    }
    combine_kernel<<<(B * 8 + 255) / 256, 256>>>(x0, B, C);
    {
        dim3 grid(C, (B + 31) / 32);
        scan_kernel<<<grid, 256>>>(Y, traj, B, T);
    }
}

// round 4
// speedup vs baseline: 1.4147x; 1.4147x over previous
#include <cuda_runtime.h>

// ---------------------------------------------------------------------------
// KF: batched square-root Kalman filter. B=2048, T=1000, n=d=8.
// Chunked linear-scan decomposition; batch-per-thread matvecs with
// broadcast-LDS matrices (no shuffles, no cross-lane deps).
// ---------------------------------------------------------------------------

#define LCH  25
#define TMAX 1024
#define CMAX ((TMAX + LCH - 1) / LCH)
#define BMAX 2048

__device__ __align__(16) float g_AK[TMAX * 128];        // per t: A[64], K[64]
__device__ __align__(16) float g_W[TMAX * 64];          // suffix weights
__device__ __align__(16) float g_Phi[CMAX * 64];        // chunk transitions
__device__ __align__(16) float g_E[(size_t)CMAX * BMAX * 8];
__device__ __align__(16) float g_X[(size_t)CMAX * BMAX * 8];
__device__ float g_frozen[192];                          // A,K,P
__device__ int   g_tconv;

// ============================ riccati ======================================

__global__ void __launch_bounds__(64) riccati_kernel(
    const float* __restrict__ Fg, const float* __restrict__ Gg,
    const float* __restrict__ Hg, const float* __restrict__ Qg,
    const float* __restrict__ Rg, const float* __restrict__ P0g,
    float* __restrict__ Ps_out, int T)
{
    __shared__ float sF[72], sHF[72], sGQG[72], sC1[72], sC2[72];
    __shared__ float sP[72], sU[72], sV[72], sPn[72], sT2[72], sS[72];
    __shared__ float sK[72], sTmp[72];
    __shared__ float sRed[4];
    __shared__ int   sFlag;

    const int tid = threadIdx.x;
    const int i = tid >> 3, j = tid & 7;
    const int ij = i * 9 + j;

    sF[ij] = Fg[tid]; sTmp[ij] = Gg[tid]; sU[ij] = Qg[tid];
    sC2[ij] = Rg[tid]; sP[ij] = P0g[tid]; sV[ij] = Hg[tid];
    if (tid == 0) sFlag = 0;
    __syncthreads();

    // GQ -> sPn ; HF -> sHF
    {
        float a = 0.f, b = 0.f;
        #pragma unroll
        for (int k = 0; k < 8; k++) {
            a += sTmp[i*9+k] * sU[k*9+j];
            b += sV[i*9+k]   * sF[k*9+j];
        }
        sPn[ij] = a; sHF[ij] = b;
    }
    __syncthreads();
    {   // GQG = GQ * G^T
        float a = 0.f;
        #pragma unroll
        for (int k = 0; k < 8; k++) a += sPn[i*9+k] * sTmp[j*9+k];
        sGQG[ij] = a;
    }
    __syncthreads();
    {   // C1 = H * GQG
        float a = 0.f;
        #pragma unroll
        for (int k = 0; k < 8; k++) a += sV[i*9+k] * sGQG[k*9+j];
        sC1[ij] = a;
    }
    __syncthreads();
    {   // C2 = C1 * H^T + R
        float a = sC2[ij];
        #pragma unroll
        for (int k = 0; k < 8; k++) a += sC1[i*9+k] * sV[j*9+k];
        __syncthreads();
        sC2[ij] = a;
    }
    __syncthreads();

    int conv = 0;
    bool frozen = false;
    for (int t = 0; t < T; t++) {
        {   // U = F*P ; V = HF*P
            float a = 0.f, b = 0.f;
            #pragma unroll
            for (int k = 0; k < 8; k++) {
                float p = sP[k*9+j];
                a = fmaf(sF[i*9+k],  p, a);
                b = fmaf(sHF[i*9+k], p, b);
            }
            sU[ij] = a; sV[ij] = b;
        }
        __syncthreads();
        {   // Pn = U*F^T + GQG ; T2 = V*F^T + C1 ; S = V*HF^T + C2
            float pn = sGQG[ij], t2 = sC1[ij], s = sC2[ij];
            #pragma unroll
            for (int k = 0; k < 8; k++) {
                float fk = sF[j*9+k];
                float vk = sV[i*9+k];
                pn = fmaf(sU[i*9+k], fk, pn);
                t2 = fmaf(vk, fk, t2);
                s  = fmaf(vk, sHF[j*9+k], s);
            }
            sPn[ij] = pn; sT2[ij] = t2; sS[ij] = s;
        }
        __syncthreads();
        // Gauss-Jordan on [S | T2]: solves S X = T2 (S SPD, no pivoting).
        if (tid < 16) {
            float a[8];
            #pragma unroll
            for (int r = 0; r < 8; r++)
                a[r] = (tid < 8) ? sS[r*9+tid] : sT2[r*9+(tid-8)];
            #pragma unroll
            for (int p = 0; p < 8; p++) {
                float c[8];
                #pragma unroll
                for (int r = 0; r < 8; r++)
                    c[r] = __shfl_sync(0x0000FFFFu, a[r], p, 16);
                float pr = 1.0f / c[p];
                a[p] *= pr;
                #pragma unroll
                for (int r = 0; r < 8; r++)
                    if (r != p) a[r] = fmaf(-c[r], a[p], a[r]);
            }
            if (tid >= 8) {
                const int row = tid - 8;
                #pragma unroll
                for (int r = 0; r < 8; r++) sK[row*9 + r] = a[r];
            }
        }
        __syncthreads();
        // P+ = Pn - K*T2 ; A = F - K*HF
        float krow[8];
        #pragma unroll
        for (int k = 0; k < 8; k++) krow[k] = sK[i*9+k];
        float pp = sPn[ij], aa = sF[ij];
        #pragma unroll
        for (int k = 0; k < 8; k++) {
            pp = fmaf(-krow[k], sT2[k*9+j], pp);
            aa = fmaf(-krow[k], sHF[k*9+j], aa);
        }
        sTmp[ij] = pp;
        __syncthreads();
        float pnew = 0.5f * (pp + sTmp[j*9+i]);
        float pold = sP[ij];
        sP[ij] = pnew;

        Ps_out[(size_t)t*64 + tid]          = pnew;
        g_AK[(size_t)t*128 + i*8 + j]       = aa;
        g_AK[(size_t)t*128 + 64 + i*8 + j]  = krow[j];

        float dm = fabsf(pnew - pold);
        float pm = fabsf(pnew);
        #pragma unroll
        for (int o = 16; o > 0; o >>= 1) {
            dm = fmaxf(dm, __shfl_xor_sync(0xFFFFFFFFu, dm, o));
            pm = fmaxf(pm, __shfl_xor_sync(0xFFFFFFFFu, pm, o));
        }
        if ((tid & 31) == 0) { sRed[(tid>>5)*2] = dm; sRed[(tid>>5)*2+1] = pm; }
        __syncthreads();
        if (tid == 0) {
            float d = fmaxf(sRed[0], sRed[2]);
            float p = fmaxf(sRed[1], sRed[3]);
            if (t >= 16 && d < 1e-4f * p) conv++; else conv = 0;
            sFlag = (conv >= 3) ? 1 : 0;
        }
        __syncthreads();
        if (sFlag) {
            g_frozen[tid]       = aa;
            g_frozen[64 + tid]  = krow[j];
            g_frozen[128 + tid] = pnew;
            if (tid == 0) g_tconv = t + 1;
            frozen = true;
            break;
        }
    }
    if (!frozen && tid == 0) g_tconv = T;
}

// ============================ fill =========================================

__global__ void __launch_bounds__(256) fill_kernel(float* __restrict__ Ps_out, int T)
{
    const int tc = g_tconv;
    const int idx = blockIdx.x * 256 + threadIdx.x;
    const int t = idx / 192, e = idx - t * 192;
    if (t >= T || t < tc) return;
    const float v = g_frozen[e];
    if (e < 128) g_AK[(size_t)t*128 + e] = v;
    else         Ps_out[(size_t)t*64 + (e - 128)] = v;
}

// ============================ wprep ========================================

__global__ void __launch_bounds__(64) wprep_kernel(int T)
{
    const int c = blockIdx.x;
    const int L0 = c * LCH;
    const int Lc = min(LCH, T - L0);
    __shared__ float sM[2][72], sA[72], sK2[72];
    const int tid = threadIdx.x;
    const int i = tid >> 3, j = tid & 7;
    const int ij = i * 9 + j;

    sM[0][ij] = (i == j) ? 1.f : 0.f;
    __syncthreads();
    int pb = 0;
    for (int jj = Lc - 1; jj >= 0; jj--) {
        const int t = L0 + jj;
        sA[ij]  = g_AK[(size_t)t*128 + i*8 + j];
        sK2[ij] = g_AK[(size_t)t*128 + 64 + i*8 + j];
        __syncthreads();
        float w = 0.f, m = 0.f;
        #pragma unroll
        for (int k = 0; k < 8; k++) {
            float mk = sM[pb][i*9+k];
            w = fmaf(mk, sK2[k*9+j], w);
            m = fmaf(mk, sA[k*9+j],  m);
        }
        g_W[(size_t)t*64 + i*8 + j] = w;
        sM[pb ^ 1][ij] = m;
        pb ^= 1;
        __syncthreads();
    }
    g_Phi[c*64 + i*8 + j] = sM[pb][ij];
}

// ============================ ends =========================================
// One thread per (chunk, batch). W broadcast from shared; y in registers.

__global__ void __launch_bounds__(128) ends_kernel(
    const float* __restrict__ Y, int B, int T)
{
    const int c = blockIdx.x;
    const int L0 = c * LCH;
    const int Lc = min(LCH, T - L0);
    __shared__ __align__(16) float sW[LCH * 64];
    const int tid = threadIdx.x;
    for (int e = tid; e < Lc * 16; e += 128)
        ((float4*)sW)[e] = ((const float4*)(g_W + (size_t)L0 * 64))[e];
    __syncthreads();

    const int b = blockIdx.y * 128 + tid;
    const bool ok = (b < B);
    const int bs = ok ? b : 0;
    const float4* yb = (const float4*)(Y + ((size_t)bs * T + L0) * 8);

    float acc[8];
    #pragma unroll
    for (int i = 0; i < 8; i++) acc[i] = 0.f;

    for (int jj = 0; jj < Lc; jj++) {
        const float4 y0 = yb[2*jj], y1 = yb[2*jj + 1];
        const float* w = sW + jj * 64;
        #pragma unroll
        for (int i = 0; i < 8; i++) {
            float a = acc[i];
            a = fmaf(w[i*8+0], y0.x, a);
            a = fmaf(w[i*8+1], y0.y, a);
            a = fmaf(w[i*8+2], y0.z, a);
            a = fmaf(w[i*8+3], y0.w, a);
            a = fmaf(w[i*8+4], y1.x, a);
            a = fmaf(w[i*8+5], y1.y, a);
            a = fmaf(w[i*8+6], y1.z, a);
            a = fmaf(w[i*8+7], y1.w, a);
            acc[i] = a;
        }
    }
    if (ok) {
        float4* eo = (float4*)(g_E + ((size_t)c * B + b) * 8);
        eo[0] = make_float4(acc[0], acc[1], acc[2], acc[3]);
        eo[1] = make_float4(acc[4], acc[5], acc[6], acc[7]);
    }
}

// ============================ combine ======================================
// One thread per batch; Phi broadcast from shared.

__global__ void __launch_bounds__(256) combine_kernel(
    const float* __restrict__ x0, int B, int C)
{
    __shared__ float sPhi[CMAX * 64];
    const int tid = threadIdx.x;
    for (int e = tid; e < C * 64; e += 256) sPhi[e] = g_Phi[e];
    __syncthreads();

    const int b = blockIdx.x * 256 + tid;
    const bool ok = (b < B);
    const int bs = ok ? b : 0;

    float x[8];
    {
        const float4* xp = (const float4*)(x0 + bs * 8);
        float4 a = xp[0], b4 = xp[1];
        x[0]=a.x; x[1]=a.y; x[2]=a.z; x[3]=a.w;
        x[4]=b4.x; x[5]=b4.y; x[6]=b4.z; x[7]=b4.w;
    }

    for (int c = 0; c < C; c++) {
        if (ok) {
            float4* xo = (float4*)(g_X + ((size_t)c * B + b) * 8);
            xo[0] = make_float4(x[0], x[1], x[2], x[3]);
            xo[1] = make_float4(x[4], x[5], x[6], x[7]);
        }
        const float4* ep = (const float4*)(g_E + ((size_t)c * B + bs) * 8);
        const float4 e0 = ep[0], e1 = ep[1];
        const float* pr = sPhi + c * 64;
        float xn[8];
        #pragma unroll
        for (int i = 0; i < 8; i++) {
            float a = 0.f;
            #pragma unroll
            for (int k = 0; k < 8; k++) a = fmaf(pr[i*8+k], x[k], a);
            xn[i] = a;
        }
        xn[0]+=e0.x; xn[1]+=e0.y; xn[2]+=e0.z; xn[3]+=e0.w;
        xn[4]+=e1.x; xn[5]+=e1.y; xn[6]+=e1.z; xn[7]+=e1.w;
        #pragma unroll
        for (int i = 0; i < 8; i++) x[i] = xn[i];
    }
}

// ============================ scan =========================================
// One thread per (chunk, batch): x in registers, A/K broadcast from shared.

__global__ void __launch_bounds__(128) scan_kernel(
    const float* __restrict__ Y, float* __restrict__ traj, int B, int T)
{
    const int c = blockIdx.x;
    const int L0 = c * LCH;
    const int Lc = min(LCH, T - L0);
    __shared__ __align__(16) float sAK[LCH * 128];
    const int tid = threadIdx.x;
    for (int e = tid; e < Lc * 32; e += 128)
        ((float4*)sAK)[e] = ((const float4*)(g_AK + (size_t)L0 * 128))[e];
    __syncthreads();

    const int b = blockIdx.y * 128 + tid;
    const bool ok = (b < B);
    const int bs = ok ? b : 0;

    float x[8];
    {
        const float4* xp = (const float4*)(g_X + ((size_t)c * B + bs) * 8);
        float4 a = xp[0], b4 = xp[1];
        x[0]=a.x; x[1]=a.y; x[2]=a.z; x[3]=a.w;
        x[4]=b4.x; x[5]=b4.y; x[6]=b4.z; x[7]=b4.w;
    }
    const float4* yb = (const float4*)(Y    + ((size_t)bs * T + L0) * 8);
    float4*       ob = (float4*)      (traj + ((size_t)bs * T + L0) * 8);

    for (int jj = 0; jj < Lc; jj++) {
        const float4 y0 = yb[2*jj], y1 = yb[2*jj + 1];
        const float* a = sAK + jj * 128;        // A at [0..63], K at [64..127]
        float xn[8];
        #pragma unroll
        for (int i = 0; i < 8; i++) {
            const float* ar = a + i * 8;
            const float* kr = a + 64 + i * 8;
            float s0 = fmaf(ar[0], x[0], 0.f);
            float s1 = fmaf(kr[0], y0.x, 0.f);
            s0 = fmaf(ar[1], x[1], s0);  s1 = fmaf(kr[1], y0.y, s1);
            s0 = fmaf(ar[2], x[2], s0);  s1 = fmaf(kr[2], y0.z, s1);
            s0 = fmaf(ar[3], x[3], s0);  s1 = fmaf(kr[3], y0.w, s1);
            s0 = fmaf(ar[4], x[4], s0);  s1 = fmaf(kr[4], y1.x, s1);
            s0 = fmaf(ar[5], x[5], s0);  s1 = fmaf(kr[5], y1.y, s1);
            s0 = fmaf(ar[6], x[6], s0);  s1 = fmaf(kr[6], y1.z, s1);
            s0 = fmaf(ar[7], x[7], s0);  s1 = fmaf(kr[7], y1.w, s1);
            xn[i] = s0 + s1;
        }
        #pragma unroll
        for (int i = 0; i < 8; i++) x[i] = xn[i];
        if (ok) {
            ob[2*jj]     = make_float4(x[0], x[1], x[2], x[3]);
            ob[2*jj + 1] = make_float4(x[4], x[5], x[6], x[7]);
        }
    }
}

// ============================ launch =======================================

extern "C" void kernel_launch(void* const* d_in, const int* in_sizes, int n_in,
                              void* d_out, int out_size)
{
    const float* Y  = (const float*)d_in[0];
    const float* F  = (const float*)d_in[1];
    const float* G  = (const float*)d_in[2];
    const float* H  = (const float*)d_in[3];
    const float* Q  = (const float*)d_in[4];
    const float* R  = (const float*)d_in[5];
    const float* x0 = (const float*)d_in[6];
    const float* P0 = (const float*)d_in[7];

    const int B = in_sizes[6] / 8;
    const int T = in_sizes[0] / (B * 8);
    const int C = (T + LCH - 1) / LCH;

    float* traj = (float*)d_out;                 // (B, T, 8)
    float* Ps   = traj + (size_t)B * T * 8;      // (T, 8, 8)

    riccati_kernel<<<1, 64>>>(F, G, H, Q, R, P0, Ps, T);
    fill_kernel<<<(T * 192 + 255) / 256, 256>>>(Ps, T);
    wprep_kernel<<<C, 64>>>(T);
    {
        dim3 grid(C, (B + 127) / 128);
        ends_kernel<<<grid, 128>>>(Y, B, T);
    }
    combine_kernel<<<(B + 255) / 256, 256>>>(x0, B, C);
    {
        dim3 grid(C, (B + 127) / 128);
        scan_kernel<<<grid, 128>>>(Y, traj, B, T);
    }
}